// round 1
// baseline (speedup 1.0000x reference)
#include <cuda_runtime.h>
#include <math.h>

#define H    512
#define NH   8
#define DH   64
#define NLAY 2
#define NPRED 26
#define MAXF 5
#define FFD  2048
#define BSZ  16
#define TC   10
#define NOBJ 20
#define NP   380   /* NOBJ*(NOBJ-1) */

// ---------------- scratch (device globals; no allocation) ----------------
__device__ float g_x   [BSZ*MAXF*H];
__device__ float g_qkv [BSZ*MAXF*3*H];
__device__ float g_kv  [BSZ*TC*2*H];
__device__ float g_att [BSZ*MAXF*H];
__device__ float g_proj[BSZ*MAXF*H];
__device__ float g_ffh [BSZ*MAXF*FFD];
__device__ float g_ctx [BSZ*MAXF*H];
__device__ float g_sw  [BSZ*NOBJ*H];
__device__ float g_ow  [BSZ*NOBJ*H];
__device__ float g_cw  [BSZ*MAXF*H];
__device__ __align__(16) float g_wf[27*H];
__device__ float g_bf  [27];

__device__ __forceinline__ float gelu_f(float x) {
    return 0.5f * x * (1.0f + erff(x * 0.70710678118654752440f));
}

// ---------------- generic tiled SGEMM: C[M,N] = act(A[M,K] @ W[N,ldw]^T + bias) ----------------
__global__ void gemm_kernel(const float* __restrict__ A, const float* __restrict__ W,
                            const float* __restrict__ bias, float* __restrict__ C,
                            int M, int N, int K, int ldw, int act)
{
    __shared__ float As[32][33];
    __shared__ float Ws[32][33];
    int tid = threadIdx.x;          // 256
    int tn  = tid & 31;             // lane -> n
    int tw  = tid >> 5;             // warp -> 4 m rows
    int m0 = blockIdx.y * 32;
    int n0 = blockIdx.x * 32;
    float acc[4] = {0.f, 0.f, 0.f, 0.f};

    for (int kt = 0; kt < K; kt += 32) {
        #pragma unroll
        for (int e = tid; e < 1024; e += 256) {
            int r = e >> 5, c = e & 31;
            int m = m0 + r;
            As[r][c] = (m < M) ? A[(long)m * K + kt + c] : 0.f;
        }
        #pragma unroll
        for (int e = tid; e < 1024; e += 256) {
            int r = e >> 5, c = e & 31;
            int n = n0 + r;
            Ws[r][c] = (n < N) ? W[(long)n * ldw + kt + c] : 0.f;
        }
        __syncthreads();
        #pragma unroll
        for (int kk = 0; kk < 32; kk++) {
            float w = Ws[tn][kk];
            #pragma unroll
            for (int j = 0; j < 4; j++)
                acc[j] += As[tw * 4 + j][kk] * w;
        }
        __syncthreads();
    }
    int n = n0 + tn;
    if (n < N) {
        float bv = bias ? bias[n] : 0.f;
        #pragma unroll
        for (int j = 0; j < 4; j++) {
            int m = m0 + tw * 4 + j;
            if (m < M) {
                float v = acc[j] + bv;
                if (act == 1) v = gelu_f(v);
                C[(long)m * N + n] = v;
            }
        }
    }
}

// ---------------- tiny multi-head attention: one block per (head, batch) ----------------
__global__ void attn_kernel(const float* __restrict__ q, int qstride,
                            const float* __restrict__ k, const float* __restrict__ v, int kvstride,
                            float* __restrict__ out, int ostride,
                            int Tq, int Tk, float scale)
{
    int h = blockIdx.x, b = blockIdx.y;
    __shared__ float qs[MAXF][DH], ks[TC][DH], vs[TC][DH], sc[MAXF][TC];
    int t = threadIdx.x;  // 64
    for (int i = 0; i < Tq; i++) qs[i][t] = q[(long)(b * Tq + i) * qstride + h * DH + t];
    for (int j = 0; j < Tk; j++) {
        ks[j][t] = k[(long)(b * Tk + j) * kvstride + h * DH + t];
        vs[j][t] = v[(long)(b * Tk + j) * kvstride + h * DH + t];
    }
    __syncthreads();
    if (t < Tq * Tk) {
        int ti = t / Tk, tj = t % Tk;
        float s = 0.f;
        #pragma unroll
        for (int d = 0; d < DH; d++) s += qs[ti][d] * ks[tj][d];
        sc[ti][tj] = s * scale;
    }
    __syncthreads();
    if (t < Tq) {
        float mx = -1e30f;
        for (int j = 0; j < Tk; j++) mx = fmaxf(mx, sc[t][j]);
        float sum = 0.f;
        for (int j = 0; j < Tk; j++) { float e = expf(sc[t][j] - mx); sc[t][j] = e; sum += e; }
        float inv = 1.f / sum;
        for (int j = 0; j < Tk; j++) sc[t][j] *= inv;
    }
    __syncthreads();
    for (int ti = 0; ti < Tq; ti++) {
        float o = 0.f;
        for (int j = 0; j < Tk; j++) o += sc[ti][j] * vs[j][t];
        out[(long)(b * Tq + ti) * ostride + h * DH + t] = o;
    }
}

// ---------------- layernorm (optional residual): one block per row ----------------
__global__ void ln_kernel(const float* __restrict__ x, const float* __restrict__ res,
                          const float* __restrict__ w, const float* __restrict__ b,
                          float* __restrict__ out)
{
    int row = blockIdx.x;
    int t = threadIdx.x;  // 128
    __shared__ float sm[4];
    float v[4];
    float s = 0.f;
    #pragma unroll
    for (int i = 0; i < 4; i++) {
        int c = t + i * 128;
        float val = x[row * H + c];
        if (res) val += res[row * H + c];
        v[i] = val; s += val;
    }
    #pragma unroll
    for (int o = 16; o; o >>= 1) s += __shfl_xor_sync(0xffffffffu, s, o);
    if ((t & 31) == 0) sm[t >> 5] = s;
    __syncthreads();
    float mean = (sm[0] + sm[1] + sm[2] + sm[3]) * (1.f / H);
    __syncthreads();
    float s2 = 0.f;
    #pragma unroll
    for (int i = 0; i < 4; i++) { float d = v[i] - mean; s2 += d * d; }
    #pragma unroll
    for (int o = 16; o; o >>= 1) s2 += __shfl_xor_sync(0xffffffffu, s2, o);
    if ((t & 31) == 0) sm[t >> 5] = s2;
    __syncthreads();
    float var = (sm[0] + sm[1] + sm[2] + sm[3]) * (1.f / H);
    float inv = rsqrtf(var + 1e-5f);
    #pragma unroll
    for (int i = 0; i < 4; i++) {
        int c = t + i * 128;
        out[row * H + c] = (v[i] - mean) * inv * w[c] + b[c];
    }
}

// ---------------- init x = broadcast(future_queries) ----------------
__global__ void init_x(const float* __restrict__ fq, float* __restrict__ x, int Fh)
{
    int m = blockIdx.x;
    int f = m % Fh;
    for (int c = threadIdx.x; c < H; c += blockDim.x) x[m * H + c] = fq[f * H + c];
}

// ---------------- fold pe2 into pred/ex heads: W_fused = Wc @ pe2_w ----------------
__global__ void fusew_kernel(const float* __restrict__ pred_w, const float* __restrict__ pred_b,
                             const float* __restrict__ ex_w, const float* __restrict__ ex_b,
                             const float* __restrict__ pe2_w, const float* __restrict__ pe2_b,
                             float* __restrict__ wf, float* __restrict__ bf)
{
    int j = blockIdx.x;  // 27
    const float* wc = (j < NPRED) ? (pred_w + j * H) : ex_w;
    int t = threadIdx.x; // 128
    float s0 = 0, s1 = 0, s2 = 0, s3 = 0;
    for (int o = 0; o < H; o++) {
        float w = wc[o];
        const float* pr = pe2_w + o * H;
        s0 += w * pr[t];       s1 += w * pr[t + 128];
        s2 += w * pr[t + 256]; s3 += w * pr[t + 384];
    }
    wf[j * H + t] = s0;       wf[j * H + t + 128] = s1;
    wf[j * H + t + 256] = s2; wf[j * H + t + 384] = s3;
    if (t == 0) {
        float s = (j < NPRED) ? pred_b[j] : ex_b[0];
        for (int o = 0; o < H; o++) s += wc[o] * pe2_b[o];
        bf[j] = s;
    }
}

// ---------------- fused pair head: h = gelu(sW+oW+cW), out = h @ Wf^T + bf ----------------
// one block handles 16 rows; h staged in smem; warp-per-output dot products
__global__ void pair_kernel(const float* __restrict__ sW, const float* __restrict__ oW,
                            const float* __restrict__ cW,
                            const float* __restrict__ wf, const float* __restrict__ bf,
                            float* __restrict__ out, int Fh, int Rtot)
{
    __shared__ float hs[16][H];
    int t = threadIdx.x;  // 256
    int row0 = blockIdx.x * 16;

    // phase 1: compute gelu'd hidden for 16 rows
    for (int e = t; e < 16 * H; e += 256) {
        int r = e >> 9, c = e & (H - 1);
        int row = row0 + r;
        float hv = 0.f;
        if (row < Rtot) {
            int p = row % NP;
            int bfi = row / NP;           // b*Fh + f
            int f = bfi % Fh;
            int b = bfi / Fh;
            int i = p / (NOBJ - 1);
            int jr = p % (NOBJ - 1);
            int jo = jr + (jr >= i ? 1 : 0);
            hv = sW[(b * NOBJ + i) * H + c] + oW[(b * NOBJ + jo) * H + c] + cW[(b * Fh + f) * H + c];
            hv = gelu_f(hv);
        }
        hs[r][c] = hv;
    }
    __syncthreads();

    // phase 2: 16 rows x 27 outputs, warp-per-output
    int w = t >> 5, lane = t & 31;
    for (int o = w; o < 16 * 27; o += 8) {
        int r = o & 15, j = o >> 4;
        float acc = 0.f;
        #pragma unroll
        for (int qq = 0; qq < 4; qq++) {
            int c = lane * 4 + qq * 128;
            float4 hv = *(const float4*)&hs[r][c];
            float4 wv = *(const float4*)&wf[j * H + c];
            acc += hv.x * wv.x + hv.y * wv.y + hv.z * wv.z + hv.w * wv.w;
        }
        #pragma unroll
        for (int off = 16; off; off >>= 1) acc += __shfl_xor_sync(0xffffffffu, acc, off);
        if (lane == 0) {
            int row = row0 + r;
            if (row < Rtot) {
                acc += bf[j];
                if (j < NPRED) out[(long)row * NPRED + j] = acc;          // predicate logits
                else           out[(long)Rtot * NPRED + row] = acc;       // existence logits
            }
        }
    }
}

// ---------------- host orchestration ----------------
static inline void launch_gemm(const float* A, const float* W, const float* bias, float* C,
                               int M, int N, int K, int ldw, int act)
{
    dim3 grid((N + 31) / 32, (M + 31) / 32);
    gemm_kernel<<<grid, 256>>>(A, W, bias, C, M, N, K, ldw, act);
}

extern "C" void kernel_launch(void* const* d_in, const int* in_sizes, int n_in,
                              void* d_out, int out_size)
{
    const float* tctx    = (const float*)d_in[0];   // (B,10,H)
    const float* objf    = (const float*)d_in[1];   // (B,20,H)
    const float* fq      = (const float*)d_in[2];   // (MAXF,H)
    const float* sa_in_w = (const float*)d_in[3];
    const float* sa_in_b = (const float*)d_in[4];
    const float* sa_out_w= (const float*)d_in[5];
    const float* sa_out_b= (const float*)d_in[6];
    const float* ca_in_w = (const float*)d_in[7];
    const float* ca_in_b = (const float*)d_in[8];
    const float* ca_out_w= (const float*)d_in[9];
    const float* ca_out_b= (const float*)d_in[10];
    const float* ff1_w   = (const float*)d_in[11];
    const float* ff1_b   = (const float*)d_in[12];
    const float* ff2_w   = (const float*)d_in[13];
    const float* ff2_b   = (const float*)d_in[14];
    const float* n1_w    = (const float*)d_in[15];
    const float* n1_b    = (const float*)d_in[16];
    const float* n2_w    = (const float*)d_in[17];
    const float* n2_b    = (const float*)d_in[18];
    const float* n3_w    = (const float*)d_in[19];
    const float* n3_b    = (const float*)d_in[20];
    const float* norm_w  = (const float*)d_in[21];
    const float* norm_b  = (const float*)d_in[22];
    const float* pe1_w   = (const float*)d_in[23];  // (H, 3H)
    const float* pe1_b   = (const float*)d_in[24];
    const float* pe2_w   = (const float*)d_in[25];  // (H, H)
    const float* pe2_b   = (const float*)d_in[26];
    const float* pred_w  = (const float*)d_in[27];  // (26, H)
    const float* pred_b  = (const float*)d_in[28];
    const float* ex_w    = (const float*)d_in[29];  // (1, H)
    const float* ex_b    = (const float*)d_in[30];
    (void)in_sizes; (void)n_in;

    // Fh derived host-side from output size: out = B*Fh*P*(NPRED+1)
    int Fh = out_size / (BSZ * NP * (NPRED + 1));
    if (Fh < 1) Fh = 1;
    if (Fh > MAXF) Fh = MAXF;
    int Mq = BSZ * Fh;

    float *px, *pqkv, *pkv, *patt, *pproj, *pffh, *pctx, *psw, *pow_, *pcw, *pwf, *pbf;
    cudaGetSymbolAddress((void**)&px,    g_x);
    cudaGetSymbolAddress((void**)&pqkv,  g_qkv);
    cudaGetSymbolAddress((void**)&pkv,   g_kv);
    cudaGetSymbolAddress((void**)&patt,  g_att);
    cudaGetSymbolAddress((void**)&pproj, g_proj);
    cudaGetSymbolAddress((void**)&pffh,  g_ffh);
    cudaGetSymbolAddress((void**)&pctx,  g_ctx);
    cudaGetSymbolAddress((void**)&psw,   g_sw);
    cudaGetSymbolAddress((void**)&pow_,  g_ow);
    cudaGetSymbolAddress((void**)&pcw,   g_cw);
    cudaGetSymbolAddress((void**)&pwf,   g_wf);
    cudaGetSymbolAddress((void**)&pbf,   g_bf);

    init_x<<<Mq, 128>>>(fq, px, Fh);

    const float scale = 0.125f;  // 1/sqrt(64)
    for (int l = 0; l < NLAY; l++) {
        // self-attention
        launch_gemm(px, sa_in_w + (long)l * 3 * H * H, sa_in_b + l * 3 * H, pqkv, Mq, 3 * H, H, H, 0);
        attn_kernel<<<dim3(NH, BSZ), 64>>>(pqkv, 3 * H, pqkv + H, pqkv + 2 * H, 3 * H,
                                           patt, H, Fh, Fh, scale);
        launch_gemm(patt, sa_out_w + (long)l * H * H, sa_out_b + l * H, pproj, Mq, H, H, H, 0);
        ln_kernel<<<Mq, 128>>>(px, pproj, n1_w + l * H, n1_b + l * H, px);
        // cross-attention
        launch_gemm(px, ca_in_w + (long)l * 3 * H * H, ca_in_b + l * 3 * H, pqkv, Mq, H, H, H, 0);
        launch_gemm(tctx, ca_in_w + (long)l * 3 * H * H + (long)H * H, ca_in_b + l * 3 * H + H,
                    pkv, BSZ * TC, 2 * H, H, H, 0);
        attn_kernel<<<dim3(NH, BSZ), 64>>>(pqkv, H, pkv, pkv + H, 2 * H,
                                           patt, H, Fh, TC, scale);
        launch_gemm(patt, ca_out_w + (long)l * H * H, ca_out_b + l * H, pproj, Mq, H, H, H, 0);
        ln_kernel<<<Mq, 128>>>(px, pproj, n2_w + l * H, n2_b + l * H, px);
        // FFN
        launch_gemm(px, ff1_w + (long)l * FFD * H, ff1_b + l * FFD, pffh, Mq, FFD, H, H, 1);
        launch_gemm(pffh, ff2_w + (long)l * H * FFD, ff2_b + l * H, pproj, Mq, H, FFD, FFD, 0);
        ln_kernel<<<Mq, 128>>>(px, pproj, n3_w + l * H, n3_b + l * H, px);
    }
    ln_kernel<<<Mq, 128>>>(px, nullptr, norm_w, norm_b, pctx);

    // pair head factorization: per-object / per-context projections through pe1 slices
    launch_gemm(objf, pe1_w,         nullptr, psw,  BSZ * NOBJ, H, H, 3 * H, 0);
    launch_gemm(objf, pe1_w + H,     nullptr, pow_, BSZ * NOBJ, H, H, 3 * H, 0);
    launch_gemm(pctx, pe1_w + 2 * H, pe1_b,   pcw,  Mq,         H, H, 3 * H, 0);

    fusew_kernel<<<27, 128>>>(pred_w, pred_b, ex_w, ex_b, pe2_w, pe2_b, pwf, pbf);

    int Rtot = BSZ * Fh * NP;
    pair_kernel<<<(Rtot + 15) / 16, 256>>>(psw, pow_, pcw, pwf, pbf, (float*)d_out, Fh, Rtot);
}

// round 2
// speedup vs baseline: 2.8318x; 2.8318x over previous
#include <cuda_runtime.h>
#include <math.h>

#define H    512
#define NH   8
#define DH   64
#define NLAY 2
#define NPRED 26
#define MAXF 5
#define FFD  2048
#define BSZ  16
#define TC   10
#define NOBJ 20
#define NP   380   /* NOBJ*(NOBJ-1) */

// ---------------- scratch (device globals; no allocation) ----------------
__device__ __align__(16) float g_x   [BSZ*MAXF*H];
__device__ __align__(16) float g_qkv [BSZ*MAXF*3*H];
__device__ __align__(16) float g_kv  [BSZ*TC*2*H];
__device__ __align__(16) float g_att [BSZ*MAXF*H];
__device__ __align__(16) float g_proj[BSZ*MAXF*H];
__device__ __align__(16) float g_ffh [BSZ*MAXF*FFD];
__device__ __align__(16) float g_ctx [BSZ*MAXF*H];
__device__ __align__(16) float g_sw  [BSZ*NOBJ*H];
__device__ __align__(16) float g_ow  [BSZ*NOBJ*H];
__device__ __align__(16) float g_cw  [BSZ*MAXF*H];
__device__ __align__(16) float g_wf  [27*H];
__device__ float g_bf  [27];

__device__ __forceinline__ float gelu_f(float x) {
    return 0.5f * x * (1.0f + erff(x * 0.70710678118654752440f));
}

// ---------------- warp-dot SGEMM: C[M,N] = act(A[M,K] @ W[N,ldw]^T + bias) ----------------
// Requirements: M % 8 == 0, N % 32 == 0, K % 128 == 0, 16B-aligned rows.
// Block = 128 threads (4 warps). Warp w computes an 8m x 8n tile; lanes split K
// (lane l owns float4 at k = k0 + 4*l). No shared memory, no __syncthreads.
__global__ void __launch_bounds__(128) gemm_wd(
    const float* __restrict__ A, const float* __restrict__ W,
    const float* __restrict__ bias, float* __restrict__ C,
    int M, int N, int K, int ldw, int act)
{
    int warp = threadIdx.x >> 5, lane = threadIdx.x & 31;
    int m0 = blockIdx.y * 8;
    int n0 = blockIdx.x * 32 + warp * 8;

    const float* Ab = A + (long)m0 * K + lane * 4;
    const float* Wb = W + (long)n0 * ldw + lane * 4;

    float acc[8][8];
    #pragma unroll
    for (int i = 0; i < 8; i++)
        #pragma unroll
        for (int j = 0; j < 8; j++) acc[i][j] = 0.f;

    for (int k = 0; k < K; k += 128) {
        float4 a[8];
        #pragma unroll
        for (int i = 0; i < 8; i++)
            a[i] = *(const float4*)(Ab + (long)i * K + k);
        #pragma unroll
        for (int j = 0; j < 8; j++) {
            float4 b = *(const float4*)(Wb + (long)j * ldw + k);
            #pragma unroll
            for (int i = 0; i < 8; i++) {
                acc[i][j] += a[i].x * b.x + a[i].y * b.y + a[i].z * b.z + a[i].w * b.w;
            }
        }
    }

    // butterfly-reduce each of the 64 accumulators across the 32 lanes
    #pragma unroll
    for (int i = 0; i < 8; i++)
        #pragma unroll
        for (int j = 0; j < 8; j++) {
            float v = acc[i][j];
            v += __shfl_xor_sync(0xffffffffu, v, 16);
            v += __shfl_xor_sync(0xffffffffu, v, 8);
            v += __shfl_xor_sync(0xffffffffu, v, 4);
            v += __shfl_xor_sync(0xffffffffu, v, 2);
            v += __shfl_xor_sync(0xffffffffu, v, 1);
            acc[i][j] = v;
        }

    if (lane == 0) {
        #pragma unroll
        for (int j = 0; j < 8; j++) {
            int n = n0 + j;
            float bv = bias ? bias[n] : 0.f;
            #pragma unroll
            for (int i = 0; i < 8; i++) {
                float v = acc[i][j] + bv;
                if (act == 1) v = gelu_f(v);
                C[(long)(m0 + i) * N + n] = v;
            }
        }
    }
}

// ---------------- tiny multi-head attention: one block per (head, batch) ----------------
__global__ void attn_kernel(const float* __restrict__ q, int qstride,
                            const float* __restrict__ k, const float* __restrict__ v, int kvstride,
                            float* __restrict__ out, int ostride,
                            int Tq, int Tk, float scale)
{
    int h = blockIdx.x, b = blockIdx.y;
    __shared__ float qs[MAXF][DH], ks[TC][DH], vs[TC][DH], sc[MAXF][TC];
    int t = threadIdx.x;  // 64
    for (int i = 0; i < Tq; i++) qs[i][t] = q[(long)(b * Tq + i) * qstride + h * DH + t];
    for (int j = 0; j < Tk; j++) {
        ks[j][t] = k[(long)(b * Tk + j) * kvstride + h * DH + t];
        vs[j][t] = v[(long)(b * Tk + j) * kvstride + h * DH + t];
    }
    __syncthreads();
    if (t < Tq * Tk) {
        int ti = t / Tk, tj = t % Tk;
        float s = 0.f;
        #pragma unroll
        for (int d = 0; d < DH; d++) s += qs[ti][d] * ks[tj][d];
        sc[ti][tj] = s * scale;
    }
    __syncthreads();
    if (t < Tq) {
        float mx = -1e30f;
        for (int j = 0; j < Tk; j++) mx = fmaxf(mx, sc[t][j]);
        float sum = 0.f;
        for (int j = 0; j < Tk; j++) { float e = expf(sc[t][j] - mx); sc[t][j] = e; sum += e; }
        float inv = 1.f / sum;
        for (int j = 0; j < Tk; j++) sc[t][j] *= inv;
    }
    __syncthreads();
    for (int ti = 0; ti < Tq; ti++) {
        float o = 0.f;
        for (int j = 0; j < Tk; j++) o += sc[ti][j] * vs[j][t];
        out[(long)(b * Tq + ti) * ostride + h * DH + ti * 0 + t] = o;
    }
}

// ---------------- layernorm (optional residual): one block per row ----------------
__global__ void ln_kernel(const float* __restrict__ x, const float* __restrict__ res,
                          const float* __restrict__ w, const float* __restrict__ b,
                          float* __restrict__ out)
{
    int row = blockIdx.x;
    int t = threadIdx.x;  // 128
    __shared__ float sm[4];
    float v[4];
    float s = 0.f;
    #pragma unroll
    for (int i = 0; i < 4; i++) {
        int c = t + i * 128;
        float val = x[row * H + c];
        if (res) val += res[row * H + c];
        v[i] = val; s += val;
    }
    #pragma unroll
    for (int o = 16; o; o >>= 1) s += __shfl_xor_sync(0xffffffffu, s, o);
    if ((t & 31) == 0) sm[t >> 5] = s;
    __syncthreads();
    float mean = (sm[0] + sm[1] + sm[2] + sm[3]) * (1.f / H);
    __syncthreads();
    float s2 = 0.f;
    #pragma unroll
    for (int i = 0; i < 4; i++) { float d = v[i] - mean; s2 += d * d; }
    #pragma unroll
    for (int o = 16; o; o >>= 1) s2 += __shfl_xor_sync(0xffffffffu, s2, o);
    if ((t & 31) == 0) sm[t >> 5] = s2;
    __syncthreads();
    float var = (sm[0] + sm[1] + sm[2] + sm[3]) * (1.f / H);
    float inv = rsqrtf(var + 1e-5f);
    #pragma unroll
    for (int i = 0; i < 4; i++) {
        int c = t + i * 128;
        out[row * H + c] = (v[i] - mean) * inv * w[c] + b[c];
    }
}

// ---------------- init x = broadcast(future_queries) ----------------
__global__ void init_x(const float* __restrict__ fq, float* __restrict__ x, int Fh)
{
    int m = blockIdx.x;
    int f = m % Fh;
    for (int c = threadIdx.x; c < H; c += blockDim.x) x[m * H + c] = fq[f * H + c];
}

// ---------------- fold pe2 into pred/ex heads: W_fused = Wc @ pe2_w ----------------
// block per output row j (27 blocks), 512 threads; thread c owns output column c.
__global__ void fusew_kernel(const float* __restrict__ pred_w, const float* __restrict__ pred_b,
                             const float* __restrict__ ex_w, const float* __restrict__ ex_b,
                             const float* __restrict__ pe2_w, const float* __restrict__ pe2_b,
                             float* __restrict__ wf, float* __restrict__ bf)
{
    int j = blockIdx.x;  // 27
    const float* wc = (j < NPRED) ? (pred_w + j * H) : ex_w;
    int c = threadIdx.x; // 512
    float s = 0.f;
    for (int o = 0; o < H; o++)
        s += wc[o] * pe2_w[o * H + c];
    wf[j * H + c] = s;

    // bias: bf[j] = base + sum_o wc[o]*pe2_b[o], parallel reduce
    __shared__ float sm[16];
    float bsum = wc[c] * pe2_b[c];
    #pragma unroll
    for (int o = 16; o; o >>= 1) bsum += __shfl_xor_sync(0xffffffffu, bsum, o);
    if ((c & 31) == 0) sm[c >> 5] = bsum;
    __syncthreads();
    if (c == 0) {
        float t = (j < NPRED) ? pred_b[j] : ex_b[0];
        #pragma unroll
        for (int i = 0; i < 16; i++) t += sm[i];
        bf[j] = t;
    }
}

// ---------------- fused pair head: h = gelu(sW+oW+cW), out = h @ Wf^T + bf ----------------
__global__ void __launch_bounds__(256) pair_kernel(
    const float* __restrict__ sW, const float* __restrict__ oW,
    const float* __restrict__ cW,
    const float* __restrict__ wf, const float* __restrict__ bf,
    float* __restrict__ out, int Fh, int Rtot)
{
    __shared__ float hs[16][H];
    int t = threadIdx.x;  // 256
    int row0 = blockIdx.x * 16;

    // phase 1: compute gelu'd hidden for 16 rows
    for (int e = t; e < 16 * H; e += 256) {
        int r = e >> 9, c = e & (H - 1);
        int row = row0 + r;
        float hv = 0.f;
        if (row < Rtot) {
            int p = row % NP;
            int bfi = row / NP;           // b*Fh + f
            int f = bfi % Fh;
            int b = bfi / Fh;
            int i = p / (NOBJ - 1);
            int jr = p % (NOBJ - 1);
            int jo = jr + (jr >= i ? 1 : 0);
            hv = sW[(b * NOBJ + i) * H + c] + oW[(b * NOBJ + jo) * H + c] + cW[(b * Fh + f) * H + c];
            hv = gelu_f(hv);
        }
        hs[r][c] = hv;
    }
    __syncthreads();

    // phase 2: 16 rows x 27 outputs, warp-per-output
    int w = t >> 5, lane = t & 31;
    for (int o = w; o < 16 * 27; o += 8) {
        int r = o & 15, j = o >> 4;
        float acc = 0.f;
        #pragma unroll
        for (int qq = 0; qq < 4; qq++) {
            int c = lane * 4 + qq * 128;
            float4 hv = *(const float4*)&hs[r][c];
            float4 wv = *(const float4*)&wf[j * H + c];
            acc += hv.x * wv.x + hv.y * wv.y + hv.z * wv.z + hv.w * wv.w;
        }
        #pragma unroll
        for (int off = 16; off; off >>= 1) acc += __shfl_xor_sync(0xffffffffu, acc, off);
        if (lane == 0) {
            int row = row0 + r;
            if (row < Rtot) {
                acc += bf[j];
                if (j < NPRED) out[(long)row * NPRED + j] = acc;          // predicate logits
                else           out[(long)Rtot * NPRED + row] = acc;       // existence logits
            }
        }
    }
}

// ---------------- host orchestration ----------------
static inline void launch_gemm(const float* A, const float* W, const float* bias, float* C,
                               int M, int N, int K, int ldw, int act)
{
    dim3 grid(N / 32, M / 8);
    gemm_wd<<<grid, 128>>>(A, W, bias, C, M, N, K, ldw, act);
}

extern "C" void kernel_launch(void* const* d_in, const int* in_sizes, int n_in,
                              void* d_out, int out_size)
{
    const float* tctx    = (const float*)d_in[0];   // (B,10,H)
    const float* objf    = (const float*)d_in[1];   // (B,20,H)
    const float* fq      = (const float*)d_in[2];   // (MAXF,H)
    const float* sa_in_w = (const float*)d_in[3];
    const float* sa_in_b = (const float*)d_in[4];
    const float* sa_out_w= (const float*)d_in[5];
    const float* sa_out_b= (const float*)d_in[6];
    const float* ca_in_w = (const float*)d_in[7];
    const float* ca_in_b = (const float*)d_in[8];
    const float* ca_out_w= (const float*)d_in[9];
    const float* ca_out_b= (const float*)d_in[10];
    const float* ff1_w   = (const float*)d_in[11];
    const float* ff1_b   = (const float*)d_in[12];
    const float* ff2_w   = (const float*)d_in[13];
    const float* ff2_b   = (const float*)d_in[14];
    const float* n1_w    = (const float*)d_in[15];
    const float* n1_b    = (const float*)d_in[16];
    const float* n2_w    = (const float*)d_in[17];
    const float* n2_b    = (const float*)d_in[18];
    const float* n3_w    = (const float*)d_in[19];
    const float* n3_b    = (const float*)d_in[20];
    const float* norm_w  = (const float*)d_in[21];
    const float* norm_b  = (const float*)d_in[22];
    const float* pe1_w   = (const float*)d_in[23];  // (H, 3H)
    const float* pe1_b   = (const float*)d_in[24];
    const float* pe2_w   = (const float*)d_in[25];  // (H, H)
    const float* pe2_b   = (const float*)d_in[26];
    const float* pred_w  = (const float*)d_in[27];  // (26, H)
    const float* pred_b  = (const float*)d_in[28];
    const float* ex_w    = (const float*)d_in[29];  // (1, H)
    const float* ex_b    = (const float*)d_in[30];
    (void)in_sizes; (void)n_in;

    // Fh derived host-side from output size: out = B*Fh*P*(NPRED+1)
    int Fh = out_size / (BSZ * NP * (NPRED + 1));
    if (Fh < 1) Fh = 1;
    if (Fh > MAXF) Fh = MAXF;
    int Mq = BSZ * Fh;

    float *px, *pqkv, *pkv, *patt, *pproj, *pffh, *pctx, *psw, *pow_, *pcw, *pwf, *pbf;
    cudaGetSymbolAddress((void**)&px,    g_x);
    cudaGetSymbolAddress((void**)&pqkv,  g_qkv);
    cudaGetSymbolAddress((void**)&pkv,   g_kv);
    cudaGetSymbolAddress((void**)&patt,  g_att);
    cudaGetSymbolAddress((void**)&pproj, g_proj);
    cudaGetSymbolAddress((void**)&pffh,  g_ffh);
    cudaGetSymbolAddress((void**)&pctx,  g_ctx);
    cudaGetSymbolAddress((void**)&psw,   g_sw);
    cudaGetSymbolAddress((void**)&pow_,  g_ow);
    cudaGetSymbolAddress((void**)&pcw,   g_cw);
    cudaGetSymbolAddress((void**)&pwf,   g_wf);
    cudaGetSymbolAddress((void**)&pbf,   g_bf);

    // independent of the decoder chain: fused head weights + object projections
    fusew_kernel<<<27, 512>>>(pred_w, pred_b, ex_w, ex_b, pe2_w, pe2_b, pwf, pbf);
    launch_gemm(objf, pe1_w,     nullptr, psw,  BSZ * NOBJ, H, H, 3 * H, 0);
    launch_gemm(objf, pe1_w + H, nullptr, pow_, BSZ * NOBJ, H, H, 3 * H, 0);

    init_x<<<Mq, 128>>>(fq, px, Fh);

    const float scale = 0.125f;  // 1/sqrt(64)
    for (int l = 0; l < NLAY; l++) {
        // self-attention
        launch_gemm(px, sa_in_w + (long)l * 3 * H * H, sa_in_b + l * 3 * H, pqkv, Mq, 3 * H, H, H, 0);
        attn_kernel<<<dim3(NH, BSZ), 64>>>(pqkv, 3 * H, pqkv + H, pqkv + 2 * H, 3 * H,
                                           patt, H, Fh, Fh, scale);
        launch_gemm(patt, sa_out_w + (long)l * H * H, sa_out_b + l * H, pproj, Mq, H, H, H, 0);
        ln_kernel<<<Mq, 128>>>(px, pproj, n1_w + l * H, n1_b + l * H, px);
        // cross-attention
        launch_gemm(px, ca_in_w + (long)l * 3 * H * H, ca_in_b + l * 3 * H, pqkv, Mq, H, H, H, 0);
        launch_gemm(tctx, ca_in_w + (long)l * 3 * H * H + (long)H * H, ca_in_b + l * 3 * H + H,
                    pkv, BSZ * TC, 2 * H, H, H, 0);
        attn_kernel<<<dim3(NH, BSZ), 64>>>(pqkv, H, pkv, pkv + H, 2 * H,
                                           patt, H, Fh, TC, scale);
        launch_gemm(patt, ca_out_w + (long)l * H * H, ca_out_b + l * H, pproj, Mq, H, H, H, 0);
        ln_kernel<<<Mq, 128>>>(px, pproj, n2_w + l * H, n2_b + l * H, px);
        // FFN
        launch_gemm(px, ff1_w + (long)l * FFD * H, ff1_b + l * FFD, pffh, Mq, FFD, H, H, 1);
        launch_gemm(pffh, ff2_w + (long)l * H * FFD, ff2_b + l * H, pproj, Mq, H, FFD, FFD, 0);
        ln_kernel<<<Mq, 128>>>(px, pproj, n3_w + l * H, n3_b + l * H, px);
    }
    ln_kernel<<<Mq, 128>>>(px, nullptr, norm_w, norm_b, pctx);

    // ctx projection through pe1 slice 3
    launch_gemm(pctx, pe1_w + 2 * H, pe1_b, pcw, Mq, H, H, 3 * H, 0);

    int Rtot = BSZ * Fh * NP;
    pair_kernel<<<(Rtot + 15) / 16, 256>>>(psw, pow_, pcw, pwf, pbf, (float*)d_out, Fh, Rtot);
}